// round 3
// baseline (speedup 1.0000x reference)
#include <cuda_runtime.h>
#include <cuda_bf16.h>

// Problem: N=4096, C=64, A=256
//   S[l,c] = Lambda * (w_c - w_l)^T CV[l] (w_c - w_l)   (64x64 table)
//   loss   = mean_n [ lse_c(pred[n,c] + 0.5*S[y_n,c]) - (pred[n,y_n] + 0.5*S[y_n,y_n]) ]

#define NN 4096
#define CC 64
#define AA 256
#define NB_LOSS 512   // 4096 rows / 8 rows-per-block

// scratch (no allocation allowed): S partials per a-quarter, and loss partials
__device__ float g_Spart[4][CC * CC];
__device__ float g_partial[NB_LOSS];

// ---------------------------------------------------------------------------
// Kernel A: compute S[l, c] partials.
// grid = (aq=4, l=64), block = 256 threads.
// Block (aq, l) computes, for its 64-row slice of CV[l]:
//   T[c][b] = sum_{a in slice} D[c][a] * CV[l][a][b]      (register tile 8x8/thread)
//   Spart   = Lambda * sum_b T[c][b] * D[c][b]
// where D[c][a] = W[c][a] - W[l][a].
// ---------------------------------------------------------------------------
__global__ __launch_bounds__(256, 2) void isda_sigma_kernel(
    const float* __restrict__ W,
    const float* __restrict__ CV,
    const float* __restrict__ lambda_p)
{
    __shared__ float sDq[64 * 64];    // [a_local][c] : D^T for this a-quarter
    __shared__ float sCV[16 * 256];   // [panel_row][b]

    const int l    = blockIdx.y;
    const int aq   = blockIdx.x;       // a-quarter: rows [aq*64, aq*64+64)
    const int t    = threadIdx.x;
    const int ct   = t >> 5;           // warp id 0..7 -> c-tile
    const int lane = t & 31;           // -> b-lane

    // Build D quarter transposed: sDq[a_local*64 + c] = W[c][a] - W[l][a].
    // Each thread handles one (c, a_local4) float4 chunk: 64c * 16 chunks = 1024 = 4*256.
    {
        const float4* W4 = (const float4*)W;           // [64][64] float4 rows
        #pragma unroll
        for (int i = t; i < 64 * 16; i += 256) {
            int c   = i >> 4;          // 0..63
            int q4  = i & 15;          // float4 index within the 64-wide quarter
            int a4  = aq * 16 + q4;    // float4 index within full 256-wide row
            float4 wc = W4[c * 64 + a4];
            float4 wl = W4[l * 64 + a4];
            int a_local = q4 * 4;
            sDq[(a_local + 0) * 64 + c] = wc.x - wl.x;
            sDq[(a_local + 1) * 64 + c] = wc.y - wl.y;
            sDq[(a_local + 2) * 64 + c] = wc.z - wl.z;
            sDq[(a_local + 3) * 64 + c] = wc.w - wl.w;
        }
    }

    float acc[8][8];
    #pragma unroll
    for (int i = 0; i < 8; i++)
        #pragma unroll
        for (int k = 0; k < 8; k++) acc[i][k] = 0.f;

    const float* cvbase = CV + (size_t)l * (AA * AA) + (size_t)aq * 64 * AA;

    for (int p = 0; p < 4; ++p) {
        __syncthreads();  // guards sDq build (p==0) and sCV reuse (p>0)
        // load 16 CV rows (16*256 floats = 1024 float4, 4 per thread), coalesced
        const float4* src = (const float4*)(cvbase + p * 16 * AA);
        #pragma unroll
        for (int i = 0; i < 4; i++)
            ((float4*)sCV)[t + 256 * i] = src[t + 256 * i];
        __syncthreads();

        #pragma unroll
        for (int aa = 0; aa < 16; ++aa) {
            int a_local = p * 16 + aa;
            float dv[8], cvv[8];
            #pragma unroll
            for (int i = 0; i < 8; i++)            // warp-uniform -> smem broadcast
                dv[i] = sDq[a_local * 64 + ct * 8 + i];
            #pragma unroll
            for (int k = 0; k < 8; k++)            // bank = lane -> conflict-free
                cvv[k] = sCV[aa * 256 + lane + 32 * k];
            #pragma unroll
            for (int i = 0; i < 8; i++)
                #pragma unroll
                for (int k = 0; k < 8; k++)
                    acc[i][k] = fmaf(dv[i], cvv[k], acc[i][k]);
        }
    }

    // Epilogue: contract T with D[c][b] (recomputed from L1-hot W), warp-reduce
    const float lam = *lambda_p;
    const float* Wl = W + l * AA;
    #pragma unroll
    for (int i = 0; i < 8; i++) {
        int c = ct * 8 + i;
        const float* Wc = W + c * AA;
        float s = 0.f;
        #pragma unroll
        for (int k = 0; k < 8; k++) {
            int b = lane + 32 * k;
            float db = Wc[b] - Wl[b];
            s = fmaf(acc[i][k], db, s);
        }
        #pragma unroll
        for (int off = 16; off; off >>= 1)
            s += __shfl_xor_sync(0xffffffffu, s, off);
        if (lane == 0)
            g_Spart[aq][l * CC + c] = lam * s;
    }
}

// ---------------------------------------------------------------------------
// Kernel B: fused augment + cross-entropy. One warp per sample row (C=64 ->
// 2 logits per lane). Deterministic per-block partials (no float atomics).
// labels are int32 on device (JAX default x64-disabled downcasts the
// reference's int64 request; harness delivers int32).
// ---------------------------------------------------------------------------
__global__ __launch_bounds__(256) void isda_loss_kernel(
    const float* __restrict__ pred,
    const int* __restrict__ labels)
{
    __shared__ float sb[8];
    const int w    = threadIdx.x >> 5;
    const int lane = threadIdx.x & 31;
    const int n    = blockIdx.x * 8 + w;   // always < 4096

    const int y  = labels[n] & 63;         // mask: hard guarantee vs OOB scratch reads
    const int c0 = lane;
    const int c1 = lane + 32;

    float S0 = g_Spart[0][y * CC + c0] + g_Spart[1][y * CC + c0]
             + g_Spart[2][y * CC + c0] + g_Spart[3][y * CC + c0];
    float S1 = g_Spart[0][y * CC + c1] + g_Spart[1][y * CC + c1]
             + g_Spart[2][y * CC + c1] + g_Spart[3][y * CC + c1];

    float a0 = pred[n * CC + c0] + 0.5f * S0;
    float a1 = pred[n * CC + c1] + 0.5f * S1;

    float m = fmaxf(a0, a1);
    #pragma unroll
    for (int off = 16; off; off >>= 1)
        m = fmaxf(m, __shfl_xor_sync(0xffffffffu, m, off));

    float e  = __expf(a0 - m) + __expf(a1 - m);
    float ay = (c0 == y ? a0 : 0.f) + (c1 == y ? a1 : 0.f);
    #pragma unroll
    for (int off = 16; off; off >>= 1) {
        e  += __shfl_xor_sync(0xffffffffu, e, off);
        ay += __shfl_xor_sync(0xffffffffu, ay, off);
    }

    float nll = m + __logf(e) - ay;

    if (lane == 0) sb[w] = nll;
    __syncthreads();
    if (threadIdx.x == 0) {
        float s = 0.f;
        #pragma unroll
        for (int i = 0; i < 8; i++) s += sb[i];
        g_partial[blockIdx.x] = s;
    }
}

// ---------------------------------------------------------------------------
// Kernel C: deterministic tree reduction of 512 partials -> mean
// ---------------------------------------------------------------------------
__global__ __launch_bounds__(512) void isda_final_kernel(float* __restrict__ out)
{
    __shared__ float sb[512];
    const int t = threadIdx.x;
    sb[t] = g_partial[t];
    __syncthreads();
    #pragma unroll
    for (int s = 256; s; s >>= 1) {
        if (t < s) sb[t] += sb[t + s];
        __syncthreads();
    }
    if (t == 0) out[0] = sb[0] * (1.0f / NN);
}

// ---------------------------------------------------------------------------
// Inputs (metadata order): fc_weight[64,256] f32, features[4096,256] f32 (unused),
// pred[4096,64] f32, labels[4096] i32, Lambda[1] f32, covariance_sample[64,256,256] f32
// Output: scalar f32
// ---------------------------------------------------------------------------
extern "C" void kernel_launch(void* const* d_in, const int* in_sizes, int n_in,
                              void* d_out, int out_size)
{
    const float* W      = (const float*)d_in[0];
    const float* pred   = (const float*)d_in[2];
    const int*   labels = (const int*)d_in[3];
    const float* Lam    = (const float*)d_in[4];
    const float* CV     = (const float*)d_in[5];

    isda_sigma_kernel<<<dim3(4, 64), 256>>>(W, CV, Lam);
    isda_loss_kernel<<<NB_LOSS, 256>>>(pred, labels);
    isda_final_kernel<<<1, 512>>>((float*)d_out);
}